// round 7
// baseline (speedup 1.0000x reference)
#include <cuda_runtime.h>
#include <cuda_bf16.h>
#include <stdint.h>

// Problem constants
#define BATCH 1024
#define NA    10
#define NE    11
#define AF    32
#define EF    28
#define HYP   64
#define OUTD  256

// Concatenated-K layout:
//   [0,2048) M_ally  [2048,2080) xsum_ally  [2080,3872) M_enemy
//   [3872,3900) xsum_enemy  [3900,3904) pad
#define KA      (HYP*AF)
#define OFF_FA  KA
#define OFF_ME  (KA+AF)
#define KE      (HYP*EF)
#define OFF_FE  (OFF_ME+KE)
#define KTOT    (OFF_FE+EF)
#define KP      3904
#define SPLIT   8
#define NST     (KP/32)        // 122 BK=32 stages
#define NPACK   ((KP/64)*4)    // 244 pack tiles (61 k-tiles x 4 n-tiles)

// Split-precision operands (hi + lo bf16 ~= fp32 to ~2^-17)
__device__ __align__(16) __nv_bfloat16 g_Ua_hi[BATCH * KP];   // A  [m][k]
__device__ __align__(16) __nv_bfloat16 g_Ua_lo[BATCH * KP];
__device__ __align__(16) __nv_bfloat16 g_Wt_hi[OUTD * KP];    // B^T [n][k]
__device__ __align__(16) __nv_bfloat16 g_Wt_lo[OUTD * KP];
__device__ float g_P[SPLIT * BATCH * OUTD];                   // split-K partials
__device__ int   g_cnt[32];                                   // per-tile arrival counters (zero-init)

// ---------------------------------------------------------------------------
// helpers
// ---------------------------------------------------------------------------
__device__ __forceinline__ uint32_t smem_u32(const void* p) {
    uint32_t a;
    asm("{ .reg .u64 t; cvta.to.shared.u64 t, %1; cvt.u32.u64 %0, t; }" : "=r"(a) : "l"(p));
    return a;
}
__device__ __forceinline__ void cp16(uint32_t dst, const void* src) {
    asm volatile("cp.async.cg.shared.global [%0], [%1], 16;" :: "r"(dst), "l"(src));
}
#define CP_COMMIT() asm volatile("cp.async.commit_group;" ::: "memory")
#define CP_WAIT(N)  asm volatile("cp.async.wait_group %0;" :: "n"(N) : "memory")

__device__ __forceinline__ void ldsm4(uint32_t& r0, uint32_t& r1, uint32_t& r2,
                                      uint32_t& r3, uint32_t addr) {
    asm volatile("ldmatrix.sync.aligned.m8n8.x4.shared.b16 {%0,%1,%2,%3}, [%4];"
                 : "=r"(r0), "=r"(r1), "=r"(r2), "=r"(r3) : "r"(addr));
}
__device__ __forceinline__ void mma_bf16(float* c, const uint32_t* a, const uint32_t* b) {
    asm volatile(
        "mma.sync.aligned.m16n8k16.row.col.f32.bf16.bf16.f32 "
        "{%0,%1,%2,%3},{%4,%5,%6,%7},{%8,%9},{%0,%1,%2,%3};"
        : "+f"(c[0]), "+f"(c[1]), "+f"(c[2]), "+f"(c[3])
        : "r"(a[0]), "r"(a[1]), "r"(a[2]), "r"(a[3]), "r"(b[0]), "r"(b[1]));
}

__device__ __forceinline__ void store_hilo(__nv_bfloat16* ha, __nv_bfloat16* la,
                                           size_t idx, float v) {
    __nv_bfloat16 h = __float2bfloat16(v);
    ha[idx] = h;
    la[idx] = __float2bfloat16(v - __bfloat162float(h));
}

// ---------------------------------------------------------------------------
// Kernel 1 "prep": blocks [0,NPACK) pack Wt hi/lo (transpose+convert);
// blocks [NPACK, NPACK+BATCH) build U hi/lo per batch element.
// ---------------------------------------------------------------------------
struct PrepSmem {
    union {
        float pack_s[64][65];
        struct {
            float wa1[AF * HYP];
            float we1[EF * HYP];
            float fa[NA][AF];
            float fe[NE][EF];
            float ha[NA][HYP];
            float he[NE][HYP];
        } b;
    };
};

__global__ __launch_bounds__(256) void prep(
    const float* __restrict__ fa, const float* __restrict__ fe,
    const float* __restrict__ wa1, const float* __restrict__ ba1,
    const float* __restrict__ wa2, const float* __restrict__ ba2,
    const float* __restrict__ we1, const float* __restrict__ be1,
    const float* __restrict__ we2, const float* __restrict__ be2) {

    __shared__ PrepSmem sm;
    const int t = threadIdx.x;

    if (blockIdx.x < NPACK) {
        // ---- pack: transpose + convert combined weight into Wt[n][k] ----
        const int k0 = (blockIdx.x >> 2) * 64;
        const int n0 = (blockIdx.x & 3) * 64;

        for (int i = t; i < 64 * 64; i += 256) {
            int kl = i >> 6, nl = i & 63;
            int r = k0 + kl, n = n0 + nl;
            float v;
            if (r < KA)            v = wa2[(size_t)r * OUTD + n];
            else if (r < OFF_ME)   v = ba2[(size_t)(r - KA) * OUTD + n];
            else if (r < OFF_FE)   v = we2[(size_t)(r - OFF_ME) * OUTD + n];
            else if (r < KTOT)     v = be2[(size_t)(r - OFF_FE) * OUTD + n];
            else                   v = 0.0f;
            sm.pack_s[kl][nl] = v;
        }
        __syncthreads();
        for (int i = t; i < 64 * 64; i += 256) {
            int nl = i >> 6, kl = i & 63;
            store_hilo(g_Wt_hi, g_Wt_lo, (size_t)(n0 + nl) * KP + k0 + kl, sm.pack_s[kl][nl]);
        }
        return;
    }

    // ---- build U for batch element b ----
    const int b = blockIdx.x - NPACK;
    const size_t rb = (size_t)b * KP;

    for (int i = t; i < AF * HYP; i += 256) sm.b.wa1[i] = wa1[i];
    for (int i = t; i < EF * HYP; i += 256) sm.b.we1[i] = we1[i];
    for (int i = t; i < NA * AF; i += 256) sm.b.fa[i / AF][i % AF] = fa[b * NA * AF + i];
    for (int i = t; i < NE * EF; i += 256) sm.b.fe[i / EF][i % EF] = fe[b * NE * EF + i];
    __syncthreads();

    for (int i = t; i < NA * HYP; i += 256) {
        int n = i / HYP, k = i % HYP;
        float s = ba1[k];
        #pragma unroll
        for (int f = 0; f < AF; f++) s += sm.b.fa[n][f] * sm.b.wa1[f * HYP + k];
        sm.b.ha[n][k] = fmaxf(s, 0.0f);
    }
    for (int i = t; i < NE * HYP; i += 256) {
        int n = i / HYP, k = i % HYP;
        float s = be1[k];
        #pragma unroll
        for (int f = 0; f < EF; f++) s += sm.b.fe[n][f] * sm.b.we1[f * HYP + k];
        sm.b.he[n][k] = fmaxf(s, 0.0f);
    }
    __syncthreads();

    for (int i = t; i < KA; i += 256) {
        int k = i >> 5, f = i & 31;
        float s = 0.0f;
        #pragma unroll
        for (int n = 0; n < NA; n++) s += sm.b.ha[n][k] * sm.b.fa[n][f];
        store_hilo(g_Ua_hi, g_Ua_lo, rb + i, s);
    }
    if (t < AF) {
        float s = 0.0f;
        #pragma unroll
        for (int n = 0; n < NA; n++) s += sm.b.fa[n][t];
        store_hilo(g_Ua_hi, g_Ua_lo, rb + OFF_FA + t, s);
    }
    for (int i = t; i < KE; i += 256) {
        int k = i / EF, f = i - k * EF;
        float s = 0.0f;
        #pragma unroll
        for (int n = 0; n < NE; n++) s += sm.b.he[n][k] * sm.b.fe[n][f];
        store_hilo(g_Ua_hi, g_Ua_lo, rb + OFF_ME + i, s);
    }
    if (t < EF) {
        float s = 0.0f;
        #pragma unroll
        for (int n = 0; n < NE; n++) s += sm.b.fe[n][t];
        store_hilo(g_Ua_hi, g_Ua_lo, rb + OFF_FE + t, s);
    }
    if (t < (KP - KTOT)) store_hilo(g_Ua_hi, g_Ua_lo, rb + KTOT + t, 0.0f);
}

// ---------------------------------------------------------------------------
// Kernel 2: split-precision bf16 HMMA GEMM + fused last-CTA split-K reduce.
// BM=128, BN=64, BK=32 double-buffered cp.async, 256 threads / 8 warps,
// warp tile 32x32. grid (8, 4, SPLIT) = 256 CTAs.
// ---------------------------------------------------------------------------
#define ASTRIDE 40                       // bf16 elems per row (80 B)
#define ASZ1    (128 * ASTRIDE * 2)      // bytes per A buffer = 10240
#define BSZ1    (64 * ASTRIDE * 2)       // bytes per B buffer = 5120
#define OFF_AH  0
#define OFF_AL  (2 * ASZ1)
#define OFF_BH  (4 * ASZ1)
#define OFF_BL  (4 * ASZ1 + 2 * BSZ1)
#define SMEM_DYN (4 * ASZ1 + 4 * BSZ1)   // 61440

__global__ void __launch_bounds__(256, 2) gemm_mma(float* __restrict__ out) {
    extern __shared__ char dsm[];
    __shared__ int s_old;
    const uint32_t sb = smem_u32(dsm);

    const int t    = threadIdx.x;
    const int lane = t & 31;
    const int wid  = t >> 5;
    const int wm   = (wid & 3) * 32;
    const int wn   = (wid >> 2) * 32;
    const int m0   = blockIdx.x * 128;
    const int n0   = blockIdx.y * 64;
    const int z    = blockIdx.z;
    const int s0   = (NST * z) / SPLIT;
    const int s1   = (NST * (z + 1)) / SPLIT;

    const int a_row = lane & 15;
    const int a_k8  = ((lane >> 4) & 1) * 8;
    const int b_row = (lane & 7) + ((lane >> 4) & 1) * 8;
    const int b_k8  = (lane & 8);

    float acc[2][4][4];
    #pragma unroll
    for (int i = 0; i < 2; i++)
        #pragma unroll
        for (int j = 0; j < 4; j++)
            #pragma unroll
            for (int q = 0; q < 4; q++) acc[i][j][q] = 0.0f;

    auto issue = [&](int s, int buf) {
        const int k0 = s * 32;
        #pragma unroll
        for (int q = 0; q < 2; q++) {
            int idx = t + q * 256;
            int m = idx >> 2, kc = idx & 3;
            uint32_t doff = (uint32_t)(m * ASTRIDE + kc * 8) * 2;
            const __nv_bfloat16* gh = g_Ua_hi + (size_t)(m0 + m) * KP + k0 + kc * 8;
            const __nv_bfloat16* gl = g_Ua_lo + (size_t)(m0 + m) * KP + k0 + kc * 8;
            cp16(sb + OFF_AH + buf * ASZ1 + doff, gh);
            cp16(sb + OFF_AL + buf * ASZ1 + doff, gl);
        }
        {
            int n = t >> 2, kc = t & 3;
            uint32_t doff = (uint32_t)(n * ASTRIDE + kc * 8) * 2;
            const __nv_bfloat16* gh = g_Wt_hi + (size_t)(n0 + n) * KP + k0 + kc * 8;
            const __nv_bfloat16* gl = g_Wt_lo + (size_t)(n0 + n) * KP + k0 + kc * 8;
            cp16(sb + OFF_BH + buf * BSZ1 + doff, gh);
            cp16(sb + OFF_BL + buf * BSZ1 + doff, gl);
        }
    };

    issue(s0, 0);
    CP_COMMIT();

    int buf = 0;
    for (int s = s0; s < s1; s++) {
        if (s + 1 < s1) {
            issue(s + 1, buf ^ 1);
            CP_COMMIT();
            CP_WAIT(1);
        } else {
            CP_WAIT(0);
        }
        __syncthreads();

        const uint32_t baseAh = sb + OFF_AH + buf * ASZ1;
        const uint32_t baseAl = sb + OFF_AL + buf * ASZ1;
        const uint32_t baseBh = sb + OFF_BH + buf * BSZ1;
        const uint32_t baseBl = sb + OFF_BL + buf * BSZ1;

        #pragma unroll
        for (int kk = 0; kk < 2; kk++) {
            const int kcol = kk * 16;
            uint32_t Ah[2][4], Al[2][4], Bh[4][2], Bl[4][2];
            #pragma unroll
            for (int mt = 0; mt < 2; mt++) {
                uint32_t off = (uint32_t)((wm + mt * 16 + a_row) * ASTRIDE + kcol + a_k8) * 2;
                ldsm4(Ah[mt][0], Ah[mt][1], Ah[mt][2], Ah[mt][3], baseAh + off);
                ldsm4(Al[mt][0], Al[mt][1], Al[mt][2], Al[mt][3], baseAl + off);
            }
            #pragma unroll
            for (int p = 0; p < 2; p++) {
                uint32_t off = (uint32_t)((wn + p * 16 + b_row) * ASTRIDE + kcol + b_k8) * 2;
                ldsm4(Bh[2 * p][0], Bh[2 * p][1], Bh[2 * p + 1][0], Bh[2 * p + 1][1], baseBh + off);
                ldsm4(Bl[2 * p][0], Bl[2 * p][1], Bl[2 * p + 1][0], Bl[2 * p + 1][1], baseBl + off);
            }
            #pragma unroll
            for (int mt = 0; mt < 2; mt++)
                #pragma unroll
                for (int nt = 0; nt < 4; nt++) {
                    mma_bf16(acc[mt][nt], Ah[mt], Bh[nt]);
                    mma_bf16(acc[mt][nt], Ah[mt], Bl[nt]);
                    mma_bf16(acc[mt][nt], Al[mt], Bh[nt]);
                }
        }
        __syncthreads();
        buf ^= 1;
    }

    // write this CTA's split-K partial
    float* P = g_P + (size_t)z * (BATCH * OUTD);
    const int gr  = lane >> 2;
    const int tc2 = (lane & 3) * 2;
    #pragma unroll
    for (int mt = 0; mt < 2; mt++) {
        #pragma unroll
        for (int nt = 0; nt < 4; nt++) {
            int row = m0 + wm + mt * 16 + gr;
            int col = n0 + wn + nt * 8 + tc2;
            *(float2*)(P + (size_t)row * OUTD + col) =
                make_float2(acc[mt][nt][0], acc[mt][nt][1]);
            *(float2*)(P + (size_t)(row + 8) * OUTD + col) =
                make_float2(acc[mt][nt][2], acc[mt][nt][3]);
        }
    }

    // ---- fused split-K reduction: last CTA per (m,n) tile sums partials ----
    __threadfence();
    __syncthreads();
    const int tile = blockIdx.x * 4 + blockIdx.y;
    if (t == 0) s_old = atomicAdd(&g_cnt[tile], 1);
    __syncthreads();
    if (s_old == SPLIT - 1) {
        __threadfence();                            // acquire: see peers' partials
        // reduce 128x64 tile: 2048 float4, 8 per thread
        for (int i = t; i < 128 * 64 / 4; i += 256) {
            int r = i >> 4;
            int c = (i & 15) * 4;
            size_t off = (size_t)(m0 + r) * OUTD + n0 + c;
            float4 s = *(const float4*)(g_P + off);
            #pragma unroll
            for (int zz = 1; zz < SPLIT; zz++) {
                const float4 v = *(const float4*)(g_P + (size_t)zz * (BATCH * OUTD) + off);
                s.x += v.x; s.y += v.y; s.z += v.z; s.w += v.w;
            }
            *(float4*)(out + off) = s;
        }
        __syncthreads();
        if (t == 0) g_cnt[tile] = 0;   // reset for next graph replay (stream-ordered)
    }
}

// ---------------------------------------------------------------------------
// Inputs: 0 ally 1 enemy 2 wa1 3 ba1 4 wa2 5 ba2 6 we1 7 be1 8 we2 9 be2
// ---------------------------------------------------------------------------
extern "C" void kernel_launch(void* const* d_in, const int* in_sizes, int n_in,
                              void* d_out, int out_size) {
    const float* fa  = (const float*)d_in[0];
    const float* fe  = (const float*)d_in[1];
    const float* wa1 = (const float*)d_in[2];
    const float* ba1 = (const float*)d_in[3];
    const float* wa2 = (const float*)d_in[4];
    const float* ba2 = (const float*)d_in[5];
    const float* we1 = (const float*)d_in[6];
    const float* be1 = (const float*)d_in[7];
    const float* we2 = (const float*)d_in[8];
    const float* be2 = (const float*)d_in[9];
    float* out = (float*)d_out;

    cudaFuncSetAttribute(gemm_mma, cudaFuncAttributeMaxDynamicSharedMemorySize, SMEM_DYN);

    prep<<<NPACK + BATCH, 256>>>(fa, fe, wa1, ba1, wa2, ba2, we1, be1, we2, be2);
    gemm_mma<<<dim3(BATCH / 128, OUTD / 64, SPLIT), 256, SMEM_DYN>>>(out);
}

// round 8
// speedup vs baseline: 1.0564x; 1.0564x over previous
#include <cuda_runtime.h>
#include <cuda_bf16.h>
#include <stdint.h>

// Problem constants
#define BATCH 1024
#define NA    10
#define NE    11
#define AF    32
#define EF    28
#define HYP   64
#define OUTD  256

// Concatenated-K layout:
//   [0,2048) M_ally  [2048,2080) xsum_ally  [2080,3872) M_enemy
//   [3872,3900) xsum_enemy  [3900,3904) pad
#define KA      (HYP*AF)
#define OFF_FA  KA
#define OFF_ME  (KA+AF)
#define KE      (HYP*EF)
#define OFF_FE  (OFF_ME+KE)
#define KTOT    (OFF_FE+EF)
#define KP      3904
#define SPLIT   8
#define NST     (KP/32)        // 122 BK=32 stages
#define NPACK   ((KP/64)*4)    // 244 pack tiles

// Split-precision operands (hi + lo bf16 ~= fp32 to ~2^-17)
__device__ __align__(16) __nv_bfloat16 g_Ua_hi[BATCH * KP];   // A  [m][k]
__device__ __align__(16) __nv_bfloat16 g_Ua_lo[BATCH * KP];
__device__ __align__(16) __nv_bfloat16 g_Wt_hi[OUTD * KP];    // B^T [n][k]
__device__ __align__(16) __nv_bfloat16 g_Wt_lo[OUTD * KP];
__device__ float g_P[SPLIT * BATCH * OUTD];                   // split-K partials
__device__ int   g_cnt[32];                                   // per-tile counters (zero-init)

// ---------------------------------------------------------------------------
// helpers
// ---------------------------------------------------------------------------
__device__ __forceinline__ uint32_t smem_u32(const void* p) {
    uint32_t a;
    asm("{ .reg .u64 t; cvta.to.shared.u64 t, %1; cvt.u32.u64 %0, t; }" : "=r"(a) : "l"(p));
    return a;
}
__device__ __forceinline__ void cp16(uint32_t dst, const void* src) {
    asm volatile("cp.async.cg.shared.global [%0], [%1], 16;" :: "r"(dst), "l"(src));
}
#define CP_COMMIT() asm volatile("cp.async.commit_group;" ::: "memory")
#define CP_WAIT(N)  asm volatile("cp.async.wait_group %0;" :: "n"(N) : "memory")

__device__ __forceinline__ void ldsm4(uint32_t& r0, uint32_t& r1, uint32_t& r2,
                                      uint32_t& r3, uint32_t addr) {
    asm volatile("ldmatrix.sync.aligned.m8n8.x4.shared.b16 {%0,%1,%2,%3}, [%4];"
                 : "=r"(r0), "=r"(r1), "=r"(r2), "=r"(r3) : "r"(addr));
}
__device__ __forceinline__ void mma_bf16(float* c, const uint32_t* a, const uint32_t* b) {
    asm volatile(
        "mma.sync.aligned.m16n8k16.row.col.f32.bf16.bf16.f32 "
        "{%0,%1,%2,%3},{%4,%5,%6,%7},{%8,%9},{%0,%1,%2,%3};"
        : "+f"(c[0]), "+f"(c[1]), "+f"(c[2]), "+f"(c[3])
        : "r"(a[0]), "r"(a[1]), "r"(a[2]), "r"(a[3]), "r"(b[0]), "r"(b[1]));
}

// vectorized hi/lo emitters
__device__ __forceinline__ void emit8(__nv_bfloat16* ha, __nv_bfloat16* la,
                                      size_t idx, const float* v) {
    __align__(16) __nv_bfloat16 hv[8], lv[8];
    #pragma unroll
    for (int j = 0; j < 8; j++) {
        __nv_bfloat16 h = __float2bfloat16(v[j]);
        hv[j] = h;
        lv[j] = __float2bfloat16(v[j] - __bfloat162float(h));
    }
    *(uint4*)(ha + idx) = *(const uint4*)hv;
    *(uint4*)(la + idx) = *(const uint4*)lv;
}
__device__ __forceinline__ void emit4(__nv_bfloat16* ha, __nv_bfloat16* la,
                                      size_t idx, const float* v) {
    __align__(8) __nv_bfloat16 hv[4], lv[4];
    #pragma unroll
    for (int j = 0; j < 4; j++) {
        __nv_bfloat16 h = __float2bfloat16(v[j]);
        hv[j] = h;
        lv[j] = __float2bfloat16(v[j] - __bfloat162float(h));
    }
    *(uint2*)(ha + idx) = *(const uint2*)hv;
    *(uint2*)(la + idx) = *(const uint2*)lv;
}

// ---------------------------------------------------------------------------
// Kernel 1 "prep": blocks [0,NPACK) pack Wt hi/lo; [NPACK,NPACK+BATCH) build U.
// ---------------------------------------------------------------------------
struct PrepSmem {
    union {
        float pack_s[64][65];
        struct {
            float wa1[AF * HYP];
            float we1[EF * HYP];
            float fa[NA][AF];
            float fe[NE][EF];
            float ha[NA][HYP];
            float he[NE][HYP];
        } b;
    };
};

__global__ __launch_bounds__(256) void prep(
    const float* __restrict__ fa, const float* __restrict__ fe,
    const float* __restrict__ wa1, const float* __restrict__ ba1,
    const float* __restrict__ wa2, const float* __restrict__ ba2,
    const float* __restrict__ we1, const float* __restrict__ be1,
    const float* __restrict__ we2, const float* __restrict__ be2) {

    __shared__ PrepSmem sm;
    const int t = threadIdx.x;

    if (blockIdx.x < NPACK) {
        // ---- pack: transpose + convert combined weight into Wt[n][k] ----
        const int k0 = (blockIdx.x >> 2) * 64;
        const int n0 = (blockIdx.x & 3) * 64;

        for (int i = t; i < 64 * 64; i += 256) {
            int kl = i >> 6, nl = i & 63;
            int r = k0 + kl, n = n0 + nl;
            float v;
            if (r < KA)            v = wa2[(size_t)r * OUTD + n];
            else if (r < OFF_ME)   v = ba2[(size_t)(r - KA) * OUTD + n];
            else if (r < OFF_FE)   v = we2[(size_t)(r - OFF_ME) * OUTD + n];
            else if (r < KTOT)     v = be2[(size_t)(r - OFF_FE) * OUTD + n];
            else                   v = 0.0f;
            sm.pack_s[kl][nl] = v;
        }
        __syncthreads();
        // vectorized: 512 items of 8 consecutive k
        for (int i = t; i < 512; i += 256) {
            int nl = i >> 3, kl8 = (i & 7) * 8;
            float v[8];
            #pragma unroll
            for (int j = 0; j < 8; j++) v[j] = sm.pack_s[kl8 + j][nl];
            emit8(g_Wt_hi, g_Wt_lo, (size_t)(n0 + nl) * KP + k0 + kl8, v);
        }
        return;
    }

    // ---- build U for batch element b ----
    const int b = blockIdx.x - NPACK;
    const size_t rb = (size_t)b * KP;

    for (int i = t; i < AF * HYP; i += 256) sm.b.wa1[i] = wa1[i];
    for (int i = t; i < EF * HYP; i += 256) sm.b.we1[i] = we1[i];
    for (int i = t; i < NA * AF; i += 256) sm.b.fa[i / AF][i % AF] = fa[b * NA * AF + i];
    for (int i = t; i < NE * EF; i += 256) sm.b.fe[i / EF][i % EF] = fe[b * NE * EF + i];
    __syncthreads();

    for (int i = t; i < NA * HYP; i += 256) {
        int n = i / HYP, k = i % HYP;
        float s = ba1[k];
        #pragma unroll
        for (int f = 0; f < AF; f++) s += sm.b.fa[n][f] * sm.b.wa1[f * HYP + k];
        sm.b.ha[n][k] = fmaxf(s, 0.0f);
    }
    for (int i = t; i < NE * HYP; i += 256) {
        int n = i / HYP, k = i % HYP;
        float s = be1[k];
        #pragma unroll
        for (int f = 0; f < EF; f++) s += sm.b.fe[n][f] * sm.b.we1[f * HYP + k];
        sm.b.he[n][k] = fmaxf(s, 0.0f);
    }
    __syncthreads();

    // ally outer products: 256 items = k(64) x f8(4), 8-wide
    {
        int k = t >> 2, f8 = (t & 3) * 8;
        float s[8] = {};
        #pragma unroll
        for (int n = 0; n < NA; n++) {
            float h = sm.b.ha[n][k];
            #pragma unroll
            for (int j = 0; j < 8; j++) s[j] += h * sm.b.fa[n][f8 + j];
        }
        emit8(g_Ua_hi, g_Ua_lo, rb + k * AF + f8, s);
    }
    // enemy outer products: 448 items = k(64) x f4(7), 4-wide
    for (int it = t; it < 448; it += 256) {
        int k = it / 7, f4 = (it - k * 7) * 4;
        float s[4] = {};
        #pragma unroll
        for (int n = 0; n < NE; n++) {
            float h = sm.b.he[n][k];
            #pragma unroll
            for (int j = 0; j < 4; j++) s[j] += h * sm.b.fe[n][f4 + j];
        }
        emit4(g_Ua_hi, g_Ua_lo, rb + OFF_ME + k * EF + f4, s);
    }
    // xsum_ally (32): 4 threads x 8-wide
    if (t < 4) {
        int f8 = t * 8;
        float s[8] = {};
        #pragma unroll
        for (int n = 0; n < NA; n++)
            #pragma unroll
            for (int j = 0; j < 8; j++) s[j] += sm.b.fa[n][f8 + j];
        emit8(g_Ua_hi, g_Ua_lo, rb + OFF_FA + f8, s);
    } else if (t >= 8 && t < 15) {
        // xsum_enemy (28): 7 threads x 4-wide
        int f4 = (t - 8) * 4;
        float s[4] = {};
        #pragma unroll
        for (int n = 0; n < NE; n++)
            #pragma unroll
            for (int j = 0; j < 4; j++) s[j] += sm.b.fe[n][f4 + j];
        emit4(g_Ua_hi, g_Ua_lo, rb + OFF_FE + f4, s);
    } else if (t == 16) {
        // pad [3900,3904)
        float s[4] = {};
        emit4(g_Ua_hi, g_Ua_lo, rb + KTOT, s);
    }
}

// ---------------------------------------------------------------------------
// Kernel 2: split-precision bf16 HMMA GEMM, 3-stage cp.async ring,
// single __syncthreads per stage, fused last-CTA split-K reduce.
// BM=128, BN=64, BK=32, 256 threads / 8 warps, warp tile 32x32.
// grid (8, 4, SPLIT) = 256 CTAs.
// ---------------------------------------------------------------------------
#define ASTRIDE 40                       // bf16 elems per row (80 B)
#define ASZ1    (128 * ASTRIDE * 2)      // 10240 B per A stage per array
#define BSZ1    (64 * ASTRIDE * 2)       // 5120 B per B stage per array
#define NSTG    3
#define OFF_AH  0
#define OFF_AL  (NSTG * ASZ1)            // 30720
#define OFF_BH  (2 * NSTG * ASZ1)        // 61440
#define OFF_BL  (2 * NSTG * ASZ1 + NSTG * BSZ1)  // 76800
#define SMEM_DYN (2 * NSTG * (ASZ1 + BSZ1))      // 92160

__global__ void __launch_bounds__(256, 2) gemm_mma(float* __restrict__ out) {
    extern __shared__ char dsm[];
    __shared__ int s_old;
    const uint32_t sb = smem_u32(dsm);

    const int t    = threadIdx.x;
    const int lane = t & 31;
    const int wid  = t >> 5;
    const int wm   = (wid & 3) * 32;
    const int wn   = (wid >> 2) * 32;
    const int m0   = blockIdx.x * 128;
    const int n0   = blockIdx.y * 64;
    const int z    = blockIdx.z;
    const int s0   = (NST * z) / SPLIT;
    const int s1   = (NST * (z + 1)) / SPLIT;

    const int a_row = lane & 15;
    const int a_k8  = ((lane >> 4) & 1) * 8;
    const int b_row = (lane & 7) + ((lane >> 4) & 1) * 8;
    const int b_k8  = (lane & 8);

    float acc[2][4][4];
    #pragma unroll
    for (int i = 0; i < 2; i++)
        #pragma unroll
        for (int j = 0; j < 4; j++)
            #pragma unroll
            for (int q = 0; q < 4; q++) acc[i][j][q] = 0.0f;

    auto issue = [&](int s, int stg) {
        const int k0 = s * 32;
        #pragma unroll
        for (int q = 0; q < 2; q++) {
            int idx = t + q * 256;
            int m = idx >> 2, kc = idx & 3;
            uint32_t doff = (uint32_t)(m * ASTRIDE + kc * 8) * 2;
            const __nv_bfloat16* gh = g_Ua_hi + (size_t)(m0 + m) * KP + k0 + kc * 8;
            const __nv_bfloat16* gl = g_Ua_lo + (size_t)(m0 + m) * KP + k0 + kc * 8;
            cp16(sb + OFF_AH + stg * ASZ1 + doff, gh);
            cp16(sb + OFF_AL + stg * ASZ1 + doff, gl);
        }
        {
            int n = t >> 2, kc = t & 3;
            uint32_t doff = (uint32_t)(n * ASTRIDE + kc * 8) * 2;
            const __nv_bfloat16* gh = g_Wt_hi + (size_t)(n0 + n) * KP + k0 + kc * 8;
            const __nv_bfloat16* gl = g_Wt_lo + (size_t)(n0 + n) * KP + k0 + kc * 8;
            cp16(sb + OFF_BH + stg * BSZ1 + doff, gh);
            cp16(sb + OFF_BL + stg * BSZ1 + doff, gl);
        }
    };

    // prologue: stages s0, s0+1 in flight
    issue(s0, 0);
    CP_COMMIT();
    if (s0 + 1 < s1) issue(s0 + 1, 1);
    CP_COMMIT();

    int buf = 0;
    for (int s = s0; s < s1; s++) {
        CP_WAIT(1);            // stage s landed (s+1 still in flight)
        __syncthreads();       // also: all warps finished compute(s-1)

        int nb = buf + 2; if (nb >= NSTG) nb -= NSTG;
        if (s + 2 < s1) issue(s + 2, nb);
        CP_COMMIT();           // unconditional: keeps group counting uniform

        const uint32_t baseAh = sb + OFF_AH + buf * ASZ1;
        const uint32_t baseAl = sb + OFF_AL + buf * ASZ1;
        const uint32_t baseBh = sb + OFF_BH + buf * BSZ1;
        const uint32_t baseBl = sb + OFF_BL + buf * BSZ1;

        #pragma unroll
        for (int kk = 0; kk < 2; kk++) {
            const int kcol = kk * 16;
            uint32_t Ah[2][4], Al[2][4], Bh[4][2], Bl[4][2];
            #pragma unroll
            for (int mt = 0; mt < 2; mt++) {
                uint32_t off = (uint32_t)((wm + mt * 16 + a_row) * ASTRIDE + kcol + a_k8) * 2;
                ldsm4(Ah[mt][0], Ah[mt][1], Ah[mt][2], Ah[mt][3], baseAh + off);
                ldsm4(Al[mt][0], Al[mt][1], Al[mt][2], Al[mt][3], baseAl + off);
            }
            #pragma unroll
            for (int p = 0; p < 2; p++) {
                uint32_t off = (uint32_t)((wn + p * 16 + b_row) * ASTRIDE + kcol + b_k8) * 2;
                ldsm4(Bh[2 * p][0], Bh[2 * p][1], Bh[2 * p + 1][0], Bh[2 * p + 1][1], baseBh + off);
                ldsm4(Bl[2 * p][0], Bl[2 * p][1], Bl[2 * p + 1][0], Bl[2 * p + 1][1], baseBl + off);
            }
            #pragma unroll
            for (int mt = 0; mt < 2; mt++)
                #pragma unroll
                for (int nt = 0; nt < 4; nt++) {
                    mma_bf16(acc[mt][nt], Ah[mt], Bh[nt]);
                    mma_bf16(acc[mt][nt], Ah[mt], Bl[nt]);
                    mma_bf16(acc[mt][nt], Al[mt], Bh[nt]);
                }
        }
        buf = (buf + 1 == NSTG) ? 0 : buf + 1;
    }

    // write this CTA's split-K partial
    float* P = g_P + (size_t)z * (BATCH * OUTD);
    const int gr  = lane >> 2;
    const int tc2 = (lane & 3) * 2;
    #pragma unroll
    for (int mt = 0; mt < 2; mt++) {
        #pragma unroll
        for (int nt = 0; nt < 4; nt++) {
            int row = m0 + wm + mt * 16 + gr;
            int col = n0 + wn + nt * 8 + tc2;
            *(float2*)(P + (size_t)row * OUTD + col) =
                make_float2(acc[mt][nt][0], acc[mt][nt][1]);
            *(float2*)(P + (size_t)(row + 8) * OUTD + col) =
                make_float2(acc[mt][nt][2], acc[mt][nt][3]);
        }
    }

    // ---- fused split-K reduction: last CTA per (m,n) tile sums partials ----
    __threadfence();
    __syncthreads();
    const int tile = blockIdx.x * 4 + blockIdx.y;
    if (t == 0) s_old = atomicAdd(&g_cnt[tile], 1);
    __syncthreads();
    if (s_old == SPLIT - 1) {
        __threadfence();   // acquire: see peers' partials
        for (int i = t; i < 128 * 64 / 4; i += 256) {
            int r = i >> 4;
            int c = (i & 15) * 4;
            size_t off = (size_t)(m0 + r) * OUTD + n0 + c;
            float4 s = *(const float4*)(g_P + off);
            #pragma unroll
            for (int zz = 1; zz < SPLIT; zz++) {
                const float4 v = *(const float4*)(g_P + (size_t)zz * (BATCH * OUTD) + off);
                s.x += v.x; s.y += v.y; s.z += v.z; s.w += v.w;
            }
            *(float4*)(out + off) = s;
        }
        __syncthreads();
        if (t == 0) g_cnt[tile] = 0;   // reset for next graph replay
    }
}

// ---------------------------------------------------------------------------
// Inputs: 0 ally 1 enemy 2 wa1 3 ba1 4 wa2 5 ba2 6 we1 7 be1 8 we2 9 be2
// ---------------------------------------------------------------------------
extern "C" void kernel_launch(void* const* d_in, const int* in_sizes, int n_in,
                              void* d_out, int out_size) {
    const float* fa  = (const float*)d_in[0];
    const float* fe  = (const float*)d_in[1];
    const float* wa1 = (const float*)d_in[2];
    const float* ba1 = (const float*)d_in[3];
    const float* wa2 = (const float*)d_in[4];
    const float* ba2 = (const float*)d_in[5];
    const float* we1 = (const float*)d_in[6];
    const float* be1 = (const float*)d_in[7];
    const float* we2 = (const float*)d_in[8];
    const float* be2 = (const float*)d_in[9];
    float* out = (float*)d_out;

    cudaFuncSetAttribute(gemm_mma, cudaFuncAttributeMaxDynamicSharedMemorySize, SMEM_DYN);

    prep<<<NPACK + BATCH, 256>>>(fa, fe, wa1, ba1, wa2, ba2, we1, be1, we2, be2);
    gemm_mma<<<dim3(BATCH / 128, OUTD / 64, SPLIT), 256, SMEM_DYN>>>(out);
}